// round 13
// baseline (speedup 1.0000x reference)
#include <cuda_runtime.h>
#include <cuda_bf16.h>
#include <cstdint>

#define BB 2
#define CC 64
#define CI 16
#define NN 6400            // 80*80
#define KSP 29             // 21 full-chunk slots + 8 half-chunk slots
#define FULL_ITEMS 2100    // 100 bqt * 21 full kchunks (keys 0..5375)
#define NITEMS 2900        // + 800 half items (8 half chunks * 100 bqt)
#define ATTN_BLOCKS 608    // 4 per SM (152 SMs on GB300)
#define L2E 1.4426950408889634f

typedef unsigned long long ull;
typedef unsigned int u32;

// ---- global scratch (no allocations allowed) ----
__device__ u32  g_Tb[BB*NN*8];              // theta*log2e bf16x2 words [b][q][8]
__device__ u32  g_Pb[BB*NN*8];              // phi bf16x2 words [b][k][8]
__device__ __nv_bfloat16 g_Gv[(size_t)BB*NN*32];   // values [b][n][32ch]
__device__ u32  g_partw[(size_t)KSP*BB*17*NN];     // partials: 16 ch-pair planes + wsum
__device__ float g_ysum[(size_t)BB*34*NN];         // reduced (34 planes; 33 used)
__device__ unsigned g_ctr;

// =================== low-level helpers ===================
__device__ __forceinline__ u32 smem_u32(const void* p) {
    u32 a; asm("{ .reg .u64 t; cvta.to.shared.u64 t, %1; cvt.u32.u64 %0, t; }"
               : "=r"(a) : "l"(p));
    return a;
}
__device__ __forceinline__ void cp16(u32 dst, const void* src) {
    asm volatile("cp.async.cg.shared.global [%0], [%1], 16;" :: "r"(dst), "l"(src));
}
#define CP_COMMIT() asm volatile("cp.async.commit_group;" ::: "memory")
#define CP_WAIT(n)  asm volatile("cp.async.wait_group %0;" :: "n"(n) : "memory")

__device__ __forceinline__ void ldsm_x4(u32& r0, u32& r1, u32& r2, u32& r3, u32 a) {
    asm volatile("ldmatrix.sync.aligned.m8n8.x4.shared.b16 {%0,%1,%2,%3}, [%4];"
                 : "=r"(r0), "=r"(r1), "=r"(r2), "=r"(r3) : "r"(a));
}
__device__ __forceinline__ void ldsm_x4t(u32& r0, u32& r1, u32& r2, u32& r3, u32 a) {
    asm volatile("ldmatrix.sync.aligned.m8n8.x4.trans.shared.b16 {%0,%1,%2,%3}, [%4];"
                 : "=r"(r0), "=r"(r1), "=r"(r2), "=r"(r3) : "r"(a));
}
__device__ __forceinline__ void mma_bf16(float* d, const u32* a, const u32* b) {
    asm volatile(
        "mma.sync.aligned.m16n8k16.row.col.f32.bf16.bf16.f32 "
        "{%0,%1,%2,%3}, {%4,%5,%6,%7}, {%8,%9}, {%0,%1,%2,%3};"
        : "+f"(d[0]), "+f"(d[1]), "+f"(d[2]), "+f"(d[3])
        : "r"(a[0]), "r"(a[1]), "r"(a[2]), "r"(a[3]), "r"(b[0]), "r"(b[1]));
}

// ---------------- f32x2 packed fast exp2 (6 FMA-pipe ops) ----------------
__device__ __forceinline__ ull fma2(ull a, ull b, ull c) {
    ull d; asm("fma.rn.f32x2 %0,%1,%2,%3;" : "=l"(d) : "l"(a), "l"(b), "l"(c)); return d;
}
__device__ __forceinline__ ull add2(ull a, ull b) {
    ull d; asm("add.rn.f32x2 %0,%1,%2;" : "=l"(d) : "l"(a), "l"(b)); return d;
}
__device__ __forceinline__ ull pk2(float f) {
    unsigned u = __float_as_uint(f); return ((ull)u << 32) | u;
}
// 2^s for 2 packed values (s already in base-2 domain).
__device__ __forceinline__ ull fexp2(ull s) {
    ull kf = add2(s, pk2(12582912.0f));               // round via 1.5*2^23
    ull nf = add2(kf, pk2(-12582912.0f));
    ull r  = fma2(nf, pk2(-1.0f), s);                 // r = s - n, |r| <= 0.5
    ull q  = fma2(pk2(5.5504109e-2f), r, pk2(2.4022651e-1f));
    q = fma2(q, r, pk2(6.9314718e-1f));
    ull e = fma2(q, r, pk2(1.0f));
    u32 klo = (u32)kf, khi = (u32)(kf >> 32);
    u32 elo = (u32)e,  ehi = (u32)(e >> 32);
    u32 rlo = elo + (klo << 23);                      // e * 2^k, exact
    u32 rhi = ehi + (khi << 23);
    return ((ull)rhi << 32) | rlo;
}
// MUFU 2^x — separate pipe from FMA, rt 8/SMSP
__device__ __forceinline__ float ex2m(float x) {
    float r; asm("ex2.approx.f32 %0, %1;" : "=f"(r) : "f"(x)); return r;
}
// pack f32x2 (lo,hi) -> bf16x2 word {lo | hi<<16}
__device__ __forceinline__ u32 packbf(ull e2) {
    u32 lo, hi, w;
    asm("mov.b64 {%0,%1}, %2;" : "=r"(lo), "=r"(hi) : "l"(e2));
    asm("cvt.rn.bf16x2.f32 %0, %1, %2;"
        : "=r"(w) : "f"(__uint_as_float(hi)), "f"(__uint_as_float(lo)));
    return w;
}
__device__ __forceinline__ u32 packbf2(float lo, float hi) {
    u32 w;
    asm("cvt.rn.bf16x2.f32 %0, %1, %2;" : "=r"(w) : "f"(hi), "f"(lo));
    return w;
}

// ================== Phase 1: projections (bf16 out) + ctr reset ==================
__global__ __launch_bounds__(128) void proj_kernel(
    const float* __restrict__ bfimg, const float* __restrict__ x,
    const float* __restrict__ w_theta, const float* __restrict__ b_theta,
    const float* __restrict__ w_phi,   const float* __restrict__ b_phi,
    const float* __restrict__ w_g,     const float* __restrict__ b_g,
    const float* __restrict__ w_gbf,   const float* __restrict__ b_gbf)
{
    if (blockIdx.x == 0 && blockIdx.y == 0 && threadIdx.x == 0) g_ctr = 0u;

    __shared__ __align__(16) float wS[4][CC*CI];
    __shared__ __align__(16) float sB[CC*32];
    __shared__ __align__(16) float sX[CC*32];
    int tid = threadIdx.x;
    for (int idx = tid; idx < CC*CI; idx += 128) {
        int i = idx / CC, c = idx % CC;
        wS[0][c*CI+i] = w_theta[idx] * L2E;    // theta pre-scaled by log2(e)
        wS[1][c*CI+i] = w_phi[idx];
        wS[2][c*CI+i] = w_g[idx];
        wS[3][c*CI+i] = w_gbf[idx];
    }
    int b  = blockIdx.y;
    int n0 = blockIdx.x * 32;
    {
        const float4* gb = (const float4*)(bfimg + (size_t)b*CC*NN + n0);
        const float4* gx = (const float4*)(x     + (size_t)b*CC*NN + n0);
        #pragma unroll
        for (int k = 0; k < 4; k++) {
            int idx = tid + k*128;
            int c = idx >> 3, f = idx & 7;
            ((float4*)sB)[c*8 + f] = gb[(size_t)c*(NN/4) + f];
            ((float4*)sX)[c*8 + f] = gx[(size_t)c*(NN/4) + f];
        }
    }
    __syncthreads();

    int w = tid >> 5, lane = tid & 31;
    int n = n0 + lane;
    const float* src  = (w == 2) ? sX : sB;
    const float* bias = (w == 0) ? b_theta : (w == 1) ? b_phi : (w == 2) ? b_g : b_gbf;
    const float* wm   = wS[w];
    float bsc = (w == 0) ? L2E : 1.0f;

    float a[CI];
    #pragma unroll
    for (int i = 0; i < CI; i++) a[i] = bias[i] * bsc;
    #pragma unroll 8
    for (int c = 0; c < CC; c++) {
        float v = src[c*32 + lane];
        #pragma unroll
        for (int i = 0; i < CI; i++)
            a[i] = fmaf(wm[c*CI+i], v, a[i]);
    }

    u32 words[8];
    #pragma unroll
    for (int i = 0; i < 8; i++)
        words[i] = packbf2(a[2*i], a[2*i+1]);

    if (w < 2) {
        u32* o = ((w == 0) ? g_Tb : g_Pb) + ((size_t)b*NN + n)*8;
        #pragma unroll
        for (int i = 0; i < 8; i++) o[i] = words[i];
    } else {
        u32* o = (u32*)(g_Gv + ((size_t)b*NN + n)*32) + (w - 2)*8;
        #pragma unroll
        for (int i = 0; i < 8; i++) o[i] = words[i];
    }
}

// ===== Phase 2: HMMA flash attention (qtile=128, occ 4, pipelined + tail items) =====
#define PHI_BYTES (128*48)
#define VROW 96
#define TILE_BYTES (PHI_BYTES + 128*VROW)

__device__ __forceinline__ void load_tile(u32 bufb, int b, int k0, int tid) {
    u32 pdst = bufb + (u32)tid*48;
    const char* psrc = (const char*)(g_Pb + ((size_t)b*NN + k0 + tid)*8);
    cp16(pdst, psrc); cp16(pdst + 16, psrc + 16);
    u32 vdst = bufb + PHI_BYTES + (u32)tid*VROW;
    const char* vsrc = (const char*)(g_Gv + ((size_t)b*NN + k0 + tid)*32);
    #pragma unroll
    for (int i = 0; i < 4; i++) cp16(vdst + 16*i, vsrc + 16*i);
}

// process one 128-key half-tile from buffer `bufb`, accumulating y
// exp split: per m-tile, j=0,1,2 packed-FMA cubic; j=3 MUFU (75/25 pipe balance)
__device__ __forceinline__ void process_half(
    u32 bufb, u32 phi_off, u32 v_off, const u32 qa[2][4], float y[2][5][4])
{
    u32 phibase = bufb + phi_off;
    u32 vbase   = bufb + PHI_BYTES + v_off;
    #pragma unroll
    for (int kq4 = 0; kq4 < 4; kq4++) {
        int kq = kq4 * 32;
        u32 pb[4][2];
        ldsm_x4(pb[0][0], pb[0][1], pb[1][0], pb[1][1], phibase + (u32)(kq)*48);
        ldsm_x4(pb[2][0], pb[2][1], pb[3][0], pb[3][1], phibase + (u32)(kq + 16)*48);

        u32 pa[2][2][4];
        #pragma unroll
        for (int m = 0; m < 2; m++) {
            float S[4][4];
            #pragma unroll
            for (int j = 0; j < 4; j++) {
                S[j][0] = S[j][1] = S[j][2] = S[j][3] = 0.0f;
                mma_bf16(S[j], qa[m], pb[j]);
            }
            // j=0,1,2: packed-FMA cubic poly
            #pragma unroll
            for (int j = 0; j < 3; j++) {
                ull p01, p23;
                asm("mov.b64 %0,{%1,%2};" : "=l"(p01) : "f"(S[j][0]), "f"(S[j][1]));
                asm("mov.b64 %0,{%1,%2};" : "=l"(p23) : "f"(S[j][2]), "f"(S[j][3]));
                ull e01 = fexp2(p01);
                ull e23 = fexp2(p23);
                if (j == 0)      { pa[m][0][0] = packbf(e01); pa[m][0][1] = packbf(e23); }
                else if (j == 1) { pa[m][0][2] = packbf(e01); pa[m][0][3] = packbf(e23); }
                else             { pa[m][1][0] = packbf(e01); pa[m][1][1] = packbf(e23); }
            }
            // j=3: MUFU ex2 (parallel pipe)
            {
                float e0 = ex2m(S[3][0]);
                float e1 = ex2m(S[3][1]);
                float e2 = ex2m(S[3][2]);
                float e3 = ex2m(S[3][3]);
                pa[m][1][2] = packbf2(e0, e1);
                pa[m][1][3] = packbf2(e2, e3);
            }
        }

        #pragma unroll
        for (int c = 0; c < 2; c++) {
            u32 row = vbase + (u32)(kq + c*16)*VROW;
            u32 vb[4][2], vw[4];
            ldsm_x4t(vb[0][0], vb[0][1], vb[1][0], vb[1][1], row);
            ldsm_x4t(vb[2][0], vb[2][1], vb[3][0], vb[3][1], row + 32);
            ldsm_x4t(vw[0], vw[1], vw[2], vw[3], row + 64);  // ones col
            #pragma unroll
            for (int m = 0; m < 2; m++) {
                #pragma unroll
                for (int nt = 0; nt < 4; nt++)
                    mma_bf16(y[m][nt], pa[m][c], vb[nt]);
                mma_bf16(y[m][4], pa[m][c], vw);   // wsum tile
            }
        }
    }
}

__device__ __forceinline__ void store_partials(
    int slot, int b, int q0w, int g, int t, const float y[2][5][4])
{
    u32* part = g_partw + ((size_t)(slot*BB + b)*17)*NN;
    #pragma unroll
    for (int m = 0; m < 2; m++) {
        int rg = q0w + m*16 + g;
        #pragma unroll
        for (int nt = 0; nt < 4; nt++) {
            int cp = nt*4 + t;            // channel pair (2cp, 2cp+1)
            part[(size_t)cp*NN + rg]     = packbf2(y[m][nt][0], y[m][nt][1]);
            part[(size_t)cp*NN + rg + 8] = packbf2(y[m][nt][2], y[m][nt][3]);
        }
        if (t == 0) {                     // wsum plane (lo half used)
            part[(size_t)16*NN + rg]     = packbf2(y[m][4][0], 0.0f);
            part[(size_t)16*NN + rg + 8] = packbf2(y[m][4][2], 0.0f);
        }
    }
}

__global__ __launch_bounds__(128, 4) void attn_kernel()
{
    __shared__ __align__(16) char smbuf[2][TILE_BYTES];
    __shared__ unsigned itemSlot[2];

    int tid  = threadIdx.x;
    int wid  = tid >> 5;
    int lane = tid & 31;
    int g = lane >> 2, t = lane & 3;
    u32 sb0 = smem_u32(smbuf[0]);
    u32 sb1 = smem_u32(smbuf[1]);

    // one-time init of the V pad region (ones column at ch32, zeros after)
    #pragma unroll
    for (int bu = 0; bu < 2; bu++) {
        u32* p = (u32*)(smbuf[bu] + PHI_BYTES + tid*VROW + 64);
        p[0] = 0x00003F80u;   // bf16(1.0) in ch32, ch33 = 0
        #pragma unroll
        for (int i = 1; i < 8; i++) p[i] = 0u;
    }

    u32 phi_off = (u32)((((lane>>4)&1)*8 + (lane&7))*48 + ((lane>>3)&1)*16);
    u32 v_off   = (u32)((((lane>>3)&1)*8 + (lane&7))*VROW + ((lane>>4)&1)*16);

    if (tid == 0) itemSlot[0] = atomicAdd(&g_ctr, 1u);
    __syncthreads();
    unsigned item = itemSlot[0];          // ATTN_BLOCKS < FULL_ITEMS so this is a full item
    {
        int kc0 = (int)(item % 21);
        int bq0 = (int)(item / 21);
        load_tile(sb0, bq0 & 1, kc0*256,       tid); CP_COMMIT();
        load_tile(sb1, bq0 & 1, kc0*256 + 128, tid); CP_COMMIT();
    }

    // ---------- phase 1: full 256-key items, cross-item pipelined ----------
    while (item < FULL_ITEMS) {
        int kc = (int)(item % 21);
        int bqt = (int)(item / 21);
        int b = bqt & 1, qt = bqt >> 1;
        int q0w = qt*128 + wid*32;

        u32 qa[2][4];
        #pragma unroll
        for (int m = 0; m < 2; m++) {
            const u32* t0 = g_Tb + ((size_t)b*NN + q0w + m*16 + g)*8;
            const u32* t8 = t0 + 8*8;
            qa[m][0] = t0[t];     qa[m][1] = t8[t];
            qa[m][2] = t0[t + 4]; qa[m][3] = t8[t + 4];
        }

        float y[2][5][4];
        #pragma unroll
        for (int m = 0; m < 2; m++)
            #pragma unroll
            for (int nt = 0; nt < 5; nt++)
                #pragma unroll
                for (int d = 0; d < 4; d++) y[m][nt][d] = 0.0f;

        CP_WAIT(1);
        __syncthreads();

        process_half(sb0, phi_off, v_off, qa, y);

        if (tid == 0) itemSlot[1] = atomicAdd(&g_ctr, 1u);

        CP_WAIT(0);
        __syncthreads();

        unsigned nxt = itemSlot[1];
        if (nxt < FULL_ITEMS) {
            int kcn = (int)(nxt % 21);
            int bn  = (int)((nxt / 21) & 1);
            load_tile(sb0, bn, kcn*256, tid); CP_COMMIT();
        }

        process_half(sb1, phi_off, v_off, qa, y);

        __syncthreads();
        if (nxt < FULL_ITEMS) {
            int kcn = (int)(nxt % 21);
            int bn  = (int)((nxt / 21) & 1);
            load_tile(sb1, bn, kcn*256 + 128, tid); CP_COMMIT();
        }

        store_partials(kc, b, q0w, g, t, y);
        item = nxt;
    }

    // ---------- phase 2: 128-key tail items (fine-grained drain) ----------
    while (item < NITEMS) {
        int idx = (int)(item - FULL_ITEMS);
        int hc  = idx & 7;            // idx % 8
        int bqt = idx >> 3;
        int b = bqt & 1, qt = bqt >> 1;
        int q0w = qt*128 + wid*32;
        int k0 = 5376 + hc*128;
        int slot = 21 + hc;

        __syncthreads();              // prior buffer reads done
        load_tile(sb0, b, k0, tid); CP_COMMIT();

        u32 qa[2][4];
        #pragma unroll
        for (int m = 0; m < 2; m++) {
            const u32* t0 = g_Tb + ((size_t)b*NN + q0w + m*16 + g)*8;
            const u32* t8 = t0 + 8*8;
            qa[m][0] = t0[t];     qa[m][1] = t8[t];
            qa[m][2] = t0[t + 4]; qa[m][3] = t8[t + 4];
        }
        float y[2][5][4];
        #pragma unroll
        for (int m = 0; m < 2; m++)
            #pragma unroll
            for (int nt = 0; nt < 5; nt++)
                #pragma unroll
                for (int d = 0; d < 4; d++) y[m][nt][d] = 0.0f;

        if (tid == 0) itemSlot[0] = atomicAdd(&g_ctr, 1u);

        CP_WAIT(0);
        __syncthreads();              // tile ready + itemSlot[0] published

        unsigned nxt = itemSlot[0];
        process_half(sb0, phi_off, v_off, qa, y);
        store_partials(slot, b, q0w, g, t, y);
        item = nxt;
    }
}

// ============ Phase 3a: parallel partial reduction (bf16x2 -> f32) ============
__global__ __launch_bounds__(256) void reduce_kernel()
{
    const size_t STR = (size_t)BB*17*NN;
    size_t idx = (size_t)blockIdx.x * 256 + threadIdx.x;   // [b][cp][n]
    const u32* p = g_partw + idx;
    float v0 = 0.0f, v1 = 0.0f;
    #pragma unroll
    for (int ks = 0; ks < KSP; ks++) {
        u32 w = p[ks*STR];
        v0 += __uint_as_float(w << 16);
        v1 += __uint_as_float(w & 0xFFFF0000u);
    }
    int b   = (int)(idx / (17*NN));
    int rem = (int)(idx - (size_t)b*17*NN);
    int cp  = rem / NN;
    int n   = rem - cp*NN;
    float* o = g_ysum + ((size_t)b*34 + 2*cp)*NN + n;
    o[0]  = v0;
    o[NN] = v1;
}

// ============ Phase 3b: folded BN(W y) + residual, 8 ch/block ============
__global__ __launch_bounds__(128) void epi_kernel(
    const float* __restrict__ bfimg, const float* __restrict__ x,
    const float* __restrict__ w_W,   const float* __restrict__ b_W,
    const float* __restrict__ gamma, const float* __restrict__ beta,
    const float* __restrict__ mean,  const float* __restrict__ var,
    float* __restrict__ out)
{
    __shared__ __align__(16) float Wp[8*CI];
    __shared__ float bp[8];
    int tid = threadIdx.x;
    int oct = blockIdx.z;             // 0..7: 8 output channels each
    int cbase = oct * 8;
    if (tid < 8) {
        int c = cbase + tid;
        float inv = rsqrtf(var[c] + 1e-5f);
        float al  = gamma[c] * inv;
        bp[tid]   = beta[c] + al * (b_W[c] - mean[c]);
    }
    if (tid < 8*CI) {
        int c = cbase + tid / CI;
        float inv = rsqrtf(var[c] + 1e-5f);
        Wp[tid] = gamma[c] * inv * w_W[c*CI + (tid % CI)];
    }
    __syncthreads();

    int b = blockIdx.y;
    int n = blockIdx.x * 128 + tid;

    const float* ys = g_ysum + (size_t)b*34*NN + n;
    float y[32];
    #pragma unroll
    for (int j = 0; j < 32; j++) y[j] = ys[(size_t)j*NN];
    float invws = 1.0f / ys[(size_t)32*NN];
    #pragma unroll
    for (int j = 0; j < 32; j++) y[j] *= invws;

    const float* xr = x     + (size_t)b*CC*NN + n;
    const float* br = bfimg + (size_t)b*CC*NN + n;
    float* o1 = out + (size_t)b*2*CC*NN + n;
    float* o2 = o1 + (size_t)CC*NN;

    #pragma unroll
    for (int ci = 0; ci < 8; ci++) {
        int c = cbase + ci;
        const float4* w4 = (const float4*)&Wp[ci*CI];
        float4 wa = w4[0], wb = w4[1], wc = w4[2], wd = w4[3];
        float base = bp[ci];
        float r1 = base + xr[(size_t)c*NN];
        float r2 = base + br[(size_t)c*NN];
        r1 = fmaf(wa.x, y[0],  r1); r1 = fmaf(wa.y, y[1],  r1);
        r1 = fmaf(wa.z, y[2],  r1); r1 = fmaf(wa.w, y[3],  r1);
        r1 = fmaf(wb.x, y[4],  r1); r1 = fmaf(wb.y, y[5],  r1);
        r1 = fmaf(wb.z, y[6],  r1); r1 = fmaf(wb.w, y[7],  r1);
        r1 = fmaf(wc.x, y[8],  r1); r1 = fmaf(wc.y, y[9],  r1);
        r1 = fmaf(wc.z, y[10], r1); r1 = fmaf(wc.w, y[11], r1);
        r1 = fmaf(wd.x, y[12], r1); r1 = fmaf(wd.y, y[13], r1);
        r1 = fmaf(wd.z, y[14], r1); r1 = fmaf(wd.w, y[15], r1);
        r2 = fmaf(wa.x, y[16], r2); r2 = fmaf(wa.y, y[17], r2);
        r2 = fmaf(wa.z, y[18], r2); r2 = fmaf(wa.w, y[19], r2);
        r2 = fmaf(wb.x, y[20], r2); r2 = fmaf(wb.y, y[21], r2);
        r2 = fmaf(wb.z, y[22], r2); r2 = fmaf(wb.w, y[23], r2);
        r2 = fmaf(wc.x, y[24], r2); r2 = fmaf(wc.y, y[25], r2);
        r2 = fmaf(wc.z, y[26], r2); r2 = fmaf(wc.w, y[27], r2);
        r2 = fmaf(wd.x, y[28], r2); r2 = fmaf(wd.y, y[29], r2);
        r2 = fmaf(wd.z, y[30], r2); r2 = fmaf(wd.w, y[31], r2);
        o1[(size_t)c*NN] = r1;
        o2[(size_t)c*NN] = r2;
    }
}

extern "C" void kernel_launch(void* const* d_in, const int* in_sizes, int n_in,
                              void* d_out, int out_size)
{
    (void)in_sizes; (void)n_in; (void)out_size;
    const float* bfimg   = (const float*)d_in[0];
    const float* x       = (const float*)d_in[1];
    const float* w_theta = (const float*)d_in[2];
    const float* b_theta = (const float*)d_in[3];
    const float* w_phi   = (const float*)d_in[4];
    const float* b_phi   = (const float*)d_in[5];
    const float* w_g     = (const float*)d_in[6];
    const float* b_g     = (const float*)d_in[7];
    const float* w_gbf   = (const float*)d_in[8];
    const float* b_gbf   = (const float*)d_in[9];
    const float* w_W     = (const float*)d_in[10];
    const float* b_W     = (const float*)d_in[11];
    const float* gamma   = (const float*)d_in[12];
    const float* beta    = (const float*)d_in[13];
    const float* mean    = (const float*)d_in[14];
    const float* var     = (const float*)d_in[15];
    float* out = (float*)d_out;

    dim3 g1(NN/32, BB);
    proj_kernel<<<g1, 128>>>(bfimg, x, w_theta, b_theta, w_phi, b_phi,
                             w_g, b_g, w_gbf, b_gbf);

    attn_kernel<<<ATTN_BLOCKS, 128>>>();

    reduce_kernel<<<(BB*17*NN)/256, 256>>>();

    dim3 g3(NN/128, BB, 8);
    epi_kernel<<<g3, 128>>>(bfimg, x, w_W, b_W, gamma, beta, mean, var, out);
}

// round 14
// speedup vs baseline: 1.0734x; 1.0734x over previous
#include <cuda_runtime.h>
#include <cuda_bf16.h>
#include <cstdint>

#define BB 2
#define CC 64
#define CI 16
#define NN 6400            // 80*80
#define KSP 25             // partial slots (key chunks of 256)
#define NITEMS 2500        // 50 qtiles(128) * 2 batches * 25 kchunks
#define ATTN_BLOCKS 608    // 4 per SM (152 SMs on GB300)
#define L2E 1.4426950408889634f

typedef unsigned long long ull;
typedef unsigned int u32;

// ---- global scratch (no allocations allowed) ----
__device__ u32  g_Tb[BB*NN*8];              // theta*log2e bf16x2 words [b][q][8]
__device__ u32  g_Pb[BB*NN*8];              // phi bf16x2 words [b][k][8]
__device__ __nv_bfloat16 g_Gv[(size_t)BB*NN*32];   // values [b][n][32ch]
__device__ u32  g_partw[(size_t)KSP*BB*17*NN];     // partials: 16 ch-pair planes + wsum
__device__ float g_ysum[(size_t)BB*34*NN];         // reduced (34 planes; 33 used)
__device__ unsigned g_ctr;

// =================== low-level helpers ===================
__device__ __forceinline__ u32 smem_u32(const void* p) {
    u32 a; asm("{ .reg .u64 t; cvta.to.shared.u64 t, %1; cvt.u32.u64 %0, t; }"
               : "=r"(a) : "l"(p));
    return a;
}
__device__ __forceinline__ void cp16(u32 dst, const void* src) {
    asm volatile("cp.async.cg.shared.global [%0], [%1], 16;" :: "r"(dst), "l"(src));
}
#define CP_COMMIT() asm volatile("cp.async.commit_group;" ::: "memory")
#define CP_WAIT(n)  asm volatile("cp.async.wait_group %0;" :: "n"(n) : "memory")

__device__ __forceinline__ void ldsm_x4(u32& r0, u32& r1, u32& r2, u32& r3, u32 a) {
    asm volatile("ldmatrix.sync.aligned.m8n8.x4.shared.b16 {%0,%1,%2,%3}, [%4];"
                 : "=r"(r0), "=r"(r1), "=r"(r2), "=r"(r3) : "r"(a));
}
__device__ __forceinline__ void ldsm_x4t(u32& r0, u32& r1, u32& r2, u32& r3, u32 a) {
    asm volatile("ldmatrix.sync.aligned.m8n8.x4.trans.shared.b16 {%0,%1,%2,%3}, [%4];"
                 : "=r"(r0), "=r"(r1), "=r"(r2), "=r"(r3) : "r"(a));
}
__device__ __forceinline__ void mma_bf16(float* d, const u32* a, const u32* b) {
    asm volatile(
        "mma.sync.aligned.m16n8k16.row.col.f32.bf16.bf16.f32 "
        "{%0,%1,%2,%3}, {%4,%5,%6,%7}, {%8,%9}, {%0,%1,%2,%3};"
        : "+f"(d[0]), "+f"(d[1]), "+f"(d[2]), "+f"(d[3])
        : "r"(a[0]), "r"(a[1]), "r"(a[2]), "r"(a[3]), "r"(b[0]), "r"(b[1]));
}

// ---------------- f32x2 packed fast exp2 (6 FMA-pipe ops) ----------------
__device__ __forceinline__ ull fma2(ull a, ull b, ull c) {
    ull d; asm("fma.rn.f32x2 %0,%1,%2,%3;" : "=l"(d) : "l"(a), "l"(b), "l"(c)); return d;
}
__device__ __forceinline__ ull add2(ull a, ull b) {
    ull d; asm("add.rn.f32x2 %0,%1,%2;" : "=l"(d) : "l"(a), "l"(b)); return d;
}
__device__ __forceinline__ ull pk2(float f) {
    unsigned u = __float_as_uint(f); return ((ull)u << 32) | u;
}
// 2^s for 2 packed values (s already in base-2 domain).
__device__ __forceinline__ ull fexp2(ull s) {
    ull kf = add2(s, pk2(12582912.0f));               // round via 1.5*2^23
    ull nf = add2(kf, pk2(-12582912.0f));
    ull r  = fma2(nf, pk2(-1.0f), s);                 // r = s - n, |r| <= 0.5
    ull q  = fma2(pk2(5.5504109e-2f), r, pk2(2.4022651e-1f));
    q = fma2(q, r, pk2(6.9314718e-1f));
    ull e = fma2(q, r, pk2(1.0f));
    u32 klo = (u32)kf, khi = (u32)(kf >> 32);
    u32 elo = (u32)e,  ehi = (u32)(e >> 32);
    u32 rlo = elo + (klo << 23);                      // e * 2^k, exact
    u32 rhi = ehi + (khi << 23);
    return ((ull)rhi << 32) | rlo;
}
// MUFU 2^x — separate pipe from FMA, rt 8/SMSP, 1 issue slot per value
__device__ __forceinline__ float ex2m(float x) {
    float r; asm("ex2.approx.f32 %0, %1;" : "=f"(r) : "f"(x)); return r;
}
// pack f32x2 (lo,hi) -> bf16x2 word {lo | hi<<16}
__device__ __forceinline__ u32 packbf(ull e2) {
    u32 lo, hi, w;
    asm("mov.b64 {%0,%1}, %2;" : "=r"(lo), "=r"(hi) : "l"(e2));
    asm("cvt.rn.bf16x2.f32 %0, %1, %2;"
        : "=r"(w) : "f"(__uint_as_float(hi)), "f"(__uint_as_float(lo)));
    return w;
}
__device__ __forceinline__ u32 packbf2(float lo, float hi) {
    u32 w;
    asm("cvt.rn.bf16x2.f32 %0, %1, %2;" : "=r"(w) : "f"(hi), "f"(lo));
    return w;
}

// ================== Phase 1: projections (bf16 out) + ctr reset ==================
__global__ __launch_bounds__(128) void proj_kernel(
    const float* __restrict__ bfimg, const float* __restrict__ x,
    const float* __restrict__ w_theta, const float* __restrict__ b_theta,
    const float* __restrict__ w_phi,   const float* __restrict__ b_phi,
    const float* __restrict__ w_g,     const float* __restrict__ b_g,
    const float* __restrict__ w_gbf,   const float* __restrict__ b_gbf)
{
    if (blockIdx.x == 0 && blockIdx.y == 0 && threadIdx.x == 0) g_ctr = 0u;

    __shared__ __align__(16) float wS[4][CC*CI];
    __shared__ __align__(16) float sB[CC*32];
    __shared__ __align__(16) float sX[CC*32];
    int tid = threadIdx.x;
    for (int idx = tid; idx < CC*CI; idx += 128) {
        int i = idx / CC, c = idx % CC;
        wS[0][c*CI+i] = w_theta[idx] * L2E;    // theta pre-scaled by log2(e)
        wS[1][c*CI+i] = w_phi[idx];
        wS[2][c*CI+i] = w_g[idx];
        wS[3][c*CI+i] = w_gbf[idx];
    }
    int b  = blockIdx.y;
    int n0 = blockIdx.x * 32;
    {
        const float4* gb = (const float4*)(bfimg + (size_t)b*CC*NN + n0);
        const float4* gx = (const float4*)(x     + (size_t)b*CC*NN + n0);
        #pragma unroll
        for (int k = 0; k < 4; k++) {
            int idx = tid + k*128;
            int c = idx >> 3, f = idx & 7;
            ((float4*)sB)[c*8 + f] = gb[(size_t)c*(NN/4) + f];
            ((float4*)sX)[c*8 + f] = gx[(size_t)c*(NN/4) + f];
        }
    }
    __syncthreads();

    int w = tid >> 5, lane = tid & 31;
    int n = n0 + lane;
    const float* src  = (w == 2) ? sX : sB;
    const float* bias = (w == 0) ? b_theta : (w == 1) ? b_phi : (w == 2) ? b_g : b_gbf;
    const float* wm   = wS[w];
    float bsc = (w == 0) ? L2E : 1.0f;

    float a[CI];
    #pragma unroll
    for (int i = 0; i < CI; i++) a[i] = bias[i] * bsc;
    #pragma unroll 8
    for (int c = 0; c < CC; c++) {
        float v = src[c*32 + lane];
        #pragma unroll
        for (int i = 0; i < CI; i++)
            a[i] = fmaf(wm[c*CI+i], v, a[i]);
    }

    u32 words[8];
    #pragma unroll
    for (int i = 0; i < 8; i++)
        words[i] = packbf2(a[2*i], a[2*i+1]);

    if (w < 2) {
        u32* o = ((w == 0) ? g_Tb : g_Pb) + ((size_t)b*NN + n)*8;
        #pragma unroll
        for (int i = 0; i < 8; i++) o[i] = words[i];
    } else {
        u32* o = (u32*)(g_Gv + ((size_t)b*NN + n)*32) + (w - 2)*8;
        #pragma unroll
        for (int i = 0; i < 8; i++) o[i] = words[i];
    }
}

// ===== Phase 2: HMMA flash attention (qtile=128, occ 4, cross-item pipeline) =====
#define PHI_BYTES (128*48)
#define VROW 96
#define TILE_BYTES (PHI_BYTES + 128*VROW)

__device__ __forceinline__ void load_tile(u32 bufb, int b, int k0, int tid) {
    u32 pdst = bufb + (u32)tid*48;
    const char* psrc = (const char*)(g_Pb + ((size_t)b*NN + k0 + tid)*8);
    cp16(pdst, psrc); cp16(pdst + 16, psrc + 16);
    u32 vdst = bufb + PHI_BYTES + (u32)tid*VROW;
    const char* vsrc = (const char*)(g_Gv + ((size_t)b*NN + k0 + tid)*32);
    #pragma unroll
    for (int i = 0; i < 4; i++) cp16(vdst + 16*i, vsrc + 16*i);
}

// process one 128-key half-tile from buffer `bufb`, accumulating y
// exp split: per m-tile, j=0 packed-FMA cubic; j=1,2,3 MUFU (issue-port balance)
__device__ __forceinline__ void process_half(
    u32 bufb, u32 phi_off, u32 v_off, const u32 qa[2][4], float y[2][5][4])
{
    u32 phibase = bufb + phi_off;
    u32 vbase   = bufb + PHI_BYTES + v_off;
    #pragma unroll
    for (int kq4 = 0; kq4 < 4; kq4++) {
        int kq = kq4 * 32;
        u32 pb[4][2];
        ldsm_x4(pb[0][0], pb[0][1], pb[1][0], pb[1][1], phibase + (u32)(kq)*48);
        ldsm_x4(pb[2][0], pb[2][1], pb[3][0], pb[3][1], phibase + (u32)(kq + 16)*48);

        u32 pa[2][2][4];
        #pragma unroll
        for (int m = 0; m < 2; m++) {
            float S[4][4];
            #pragma unroll
            for (int j = 0; j < 4; j++) {
                S[j][0] = S[j][1] = S[j][2] = S[j][3] = 0.0f;
                mma_bf16(S[j], qa[m], pb[j]);
            }
            // j=0: packed-FMA cubic poly (FMA pipe)
            {
                ull p01, p23;
                asm("mov.b64 %0,{%1,%2};" : "=l"(p01) : "f"(S[0][0]), "f"(S[0][1]));
                asm("mov.b64 %0,{%1,%2};" : "=l"(p23) : "f"(S[0][2]), "f"(S[0][3]));
                pa[m][0][0] = packbf(fexp2(p01));
                pa[m][0][1] = packbf(fexp2(p23));
            }
            // j=1,2,3: MUFU ex2 (1 issue slot per value, parallel pipe)
            #pragma unroll
            for (int j = 1; j < 4; j++) {
                float e0 = ex2m(S[j][0]);
                float e1 = ex2m(S[j][1]);
                float e2 = ex2m(S[j][2]);
                float e3 = ex2m(S[j][3]);
                u32 wlo = packbf2(e0, e1);
                u32 whi = packbf2(e2, e3);
                if (j == 1)      { pa[m][0][2] = wlo; pa[m][0][3] = whi; }
                else if (j == 2) { pa[m][1][0] = wlo; pa[m][1][1] = whi; }
                else             { pa[m][1][2] = wlo; pa[m][1][3] = whi; }
            }
        }

        #pragma unroll
        for (int c = 0; c < 2; c++) {
            u32 row = vbase + (u32)(kq + c*16)*VROW;
            u32 vb[4][2], vw[4];
            ldsm_x4t(vb[0][0], vb[0][1], vb[1][0], vb[1][1], row);
            ldsm_x4t(vb[2][0], vb[2][1], vb[3][0], vb[3][1], row + 32);
            ldsm_x4t(vw[0], vw[1], vw[2], vw[3], row + 64);  // ones col
            #pragma unroll
            for (int m = 0; m < 2; m++) {
                #pragma unroll
                for (int nt = 0; nt < 4; nt++)
                    mma_bf16(y[m][nt], pa[m][c], vb[nt]);
                mma_bf16(y[m][4], pa[m][c], vw);   // wsum tile
            }
        }
    }
}

__global__ __launch_bounds__(128, 4) void attn_kernel()
{
    __shared__ __align__(16) char smbuf[2][TILE_BYTES];
    __shared__ unsigned itemSlot[2];

    int tid  = threadIdx.x;
    int wid  = tid >> 5;
    int lane = tid & 31;
    int g = lane >> 2, t = lane & 3;
    u32 sb0 = smem_u32(smbuf[0]);
    u32 sb1 = smem_u32(smbuf[1]);

    // one-time init of the V pad region (ones column at ch32, zeros after)
    #pragma unroll
    for (int bu = 0; bu < 2; bu++) {
        u32* p = (u32*)(smbuf[bu] + PHI_BYTES + tid*VROW + 64);
        p[0] = 0x00003F80u;   // bf16(1.0) in ch32, ch33 = 0
        #pragma unroll
        for (int i = 1; i < 8; i++) p[i] = 0u;
    }

    u32 phi_off = (u32)((((lane>>4)&1)*8 + (lane&7))*48 + ((lane>>3)&1)*16);
    u32 v_off   = (u32)((((lane>>3)&1)*8 + (lane&7))*VROW + ((lane>>4)&1)*16);

    if (tid == 0) itemSlot[0] = atomicAdd(&g_ctr, 1u);
    __syncthreads();
    unsigned item = itemSlot[0];
    if (item < NITEMS) {
        int kc0 = item % KSP;
        int bq0 = item / KSP;
        load_tile(sb0, bq0 & 1, kc0*256,       tid); CP_COMMIT();
        load_tile(sb1, bq0 & 1, kc0*256 + 128, tid); CP_COMMIT();
    }

    while (item < NITEMS) {
        int kc = item % KSP;
        int bqt = item / KSP;
        int b = bqt & 1, qt = bqt >> 1;
        int q0w = qt*128 + wid*32;

        u32 qa[2][4];
        #pragma unroll
        for (int m = 0; m < 2; m++) {
            const u32* t0 = g_Tb + ((size_t)b*NN + q0w + m*16 + g)*8;
            const u32* t8 = t0 + 8*8;
            qa[m][0] = t0[t];     qa[m][1] = t8[t];
            qa[m][2] = t0[t + 4]; qa[m][3] = t8[t + 4];
        }

        float y[2][5][4];   // 4 value n-tiles + 1 wsum n-tile
        #pragma unroll
        for (int m = 0; m < 2; m++)
            #pragma unroll
            for (int nt = 0; nt < 5; nt++)
                #pragma unroll
                for (int d = 0; d < 4; d++) y[m][nt][d] = 0.0f;

        CP_WAIT(1);               // tile0 of current item ready
        __syncthreads();

        process_half(sb0, phi_off, v_off, qa, y);

        if (tid == 0) itemSlot[1] = atomicAdd(&g_ctr, 1u);   // prefetch next id

        CP_WAIT(0);               // tile1 ready; buf0 free
        __syncthreads();          // also publishes itemSlot[1]

        unsigned nxt = itemSlot[1];
        if (nxt < NITEMS) {       // prefetch next item's tile0 into buf0
            int kcn = nxt % KSP;
            int bn  = (nxt / KSP) & 1;
            load_tile(sb0, bn, kcn*256, tid); CP_COMMIT();
        }

        process_half(sb1, phi_off, v_off, qa, y);

        __syncthreads();          // buf1 fully consumed
        if (nxt < NITEMS) {       // prefetch next item's tile1 into buf1
            int kcn = nxt % KSP;
            int bn  = (nxt / KSP) & 1;
            load_tile(sb1, bn, kcn*256 + 128, tid); CP_COMMIT();
        }

        // ---- write partials: bf16x2-packed channel pairs (4B coalesced) ----
        u32* part = g_partw + ((size_t)(kc*BB + b)*17)*NN;
        #pragma unroll
        for (int m = 0; m < 2; m++) {
            int rg = q0w + m*16 + g;
            #pragma unroll
            for (int nt = 0; nt < 4; nt++) {
                int cp = nt*4 + t;            // channel pair (2cp, 2cp+1)
                part[(size_t)cp*NN + rg]     = packbf2(y[m][nt][0], y[m][nt][1]);
                part[(size_t)cp*NN + rg + 8] = packbf2(y[m][nt][2], y[m][nt][3]);
            }
            if (t == 0) {                     // wsum plane (lo half used)
                part[(size_t)16*NN + rg]     = packbf2(y[m][4][0], 0.0f);
                part[(size_t)16*NN + rg + 8] = packbf2(y[m][4][2], 0.0f);
            }
        }

        item = nxt;
    }
}

// ============ Phase 3a: parallel partial reduction (bf16x2 -> f32) ============
__global__ __launch_bounds__(256) void reduce_kernel()
{
    const size_t STR = (size_t)BB*17*NN;
    size_t idx = (size_t)blockIdx.x * 256 + threadIdx.x;   // [b][cp][n]
    const u32* p = g_partw + idx;
    float v0 = 0.0f, v1 = 0.0f;
    #pragma unroll
    for (int ks = 0; ks < KSP; ks++) {
        u32 w = p[ks*STR];
        v0 += __uint_as_float(w << 16);
        v1 += __uint_as_float(w & 0xFFFF0000u);
    }
    int b   = (int)(idx / (17*NN));
    int rem = (int)(idx - (size_t)b*17*NN);
    int cp  = rem / NN;
    int n   = rem - cp*NN;
    float* o = g_ysum + ((size_t)b*34 + 2*cp)*NN + n;
    o[0]  = v0;
    o[NN] = v1;
}

// ============ Phase 3b: folded BN(W y) + residual, 8 ch/block ============
__global__ __launch_bounds__(128) void epi_kernel(
    const float* __restrict__ bfimg, const float* __restrict__ x,
    const float* __restrict__ w_W,   const float* __restrict__ b_W,
    const float* __restrict__ gamma, const float* __restrict__ beta,
    const float* __restrict__ mean,  const float* __restrict__ var,
    float* __restrict__ out)
{
    __shared__ __align__(16) float Wp[8*CI];
    __shared__ float bp[8];
    int tid = threadIdx.x;
    int oct = blockIdx.z;             // 0..7: 8 output channels each
    int cbase = oct * 8;
    if (tid < 8) {
        int c = cbase + tid;
        float inv = rsqrtf(var[c] + 1e-5f);
        float al  = gamma[c] * inv;
        bp[tid]   = beta[c] + al * (b_W[c] - mean[c]);
    }
    if (tid < 8*CI) {
        int c = cbase + tid / CI;
        float inv = rsqrtf(var[c] + 1e-5f);
        Wp[tid] = gamma[c] * inv * w_W[c*CI + (tid % CI)];
    }
    __syncthreads();

    int b = blockIdx.y;
    int n = blockIdx.x * 128 + tid;

    const float* ys = g_ysum + (size_t)b*34*NN + n;
    float y[32];
    #pragma unroll
    for (int j = 0; j < 32; j++) y[j] = ys[(size_t)j*NN];
    float invws = 1.0f / ys[(size_t)32*NN];
    #pragma unroll
    for (int j = 0; j < 32; j++) y[j] *= invws;

    const float* xr = x     + (size_t)b*CC*NN + n;
    const float* br = bfimg + (size_t)b*CC*NN + n;
    float* o1 = out + (size_t)b*2*CC*NN + n;
    float* o2 = o1 + (size_t)CC*NN;

    #pragma unroll
    for (int ci = 0; ci < 8; ci++) {
        int c = cbase + ci;
        const float4* w4 = (const float4*)&Wp[ci*CI];
        float4 wa = w4[0], wb = w4[1], wc = w4[2], wd = w4[3];
        float base = bp[ci];
        float r1 = base + xr[(size_t)c*NN];
        float r2 = base + br[(size_t)c*NN];
        r1 = fmaf(wa.x, y[0],  r1); r1 = fmaf(wa.y, y[1],  r1);
        r1 = fmaf(wa.z, y[2],  r1); r1 = fmaf(wa.w, y[3],  r1);
        r1 = fmaf(wb.x, y[4],  r1); r1 = fmaf(wb.y, y[5],  r1);
        r1 = fmaf(wb.z, y[6],  r1); r1 = fmaf(wb.w, y[7],  r1);
        r1 = fmaf(wc.x, y[8],  r1); r1 = fmaf(wc.y, y[9],  r1);
        r1 = fmaf(wc.z, y[10], r1); r1 = fmaf(wc.w, y[11], r1);
        r1 = fmaf(wd.x, y[12], r1); r1 = fmaf(wd.y, y[13], r1);
        r1 = fmaf(wd.z, y[14], r1); r1 = fmaf(wd.w, y[15], r1);
        r2 = fmaf(wa.x, y[16], r2); r2 = fmaf(wa.y, y[17], r2);
        r2 = fmaf(wa.z, y[18], r2); r2 = fmaf(wa.w, y[19], r2);
        r2 = fmaf(wb.x, y[20], r2); r2 = fmaf(wb.y, y[21], r2);
        r2 = fmaf(wb.z, y[22], r2); r2 = fmaf(wb.w, y[23], r2);
        r2 = fmaf(wc.x, y[24], r2); r2 = fmaf(wc.y, y[25], r2);
        r2 = fmaf(wc.z, y[26], r2); r2 = fmaf(wc.w, y[27], r2);
        r2 = fmaf(wd.x, y[28], r2); r2 = fmaf(wd.y, y[29], r2);
        r2 = fmaf(wd.z, y[30], r2); r2 = fmaf(wd.w, y[31], r2);
        o1[(size_t)c*NN] = r1;
        o2[(size_t)c*NN] = r2;
    }
}

extern "C" void kernel_launch(void* const* d_in, const int* in_sizes, int n_in,
                              void* d_out, int out_size)
{
    (void)in_sizes; (void)n_in; (void)out_size;
    const float* bfimg   = (const float*)d_in[0];
    const float* x       = (const float*)d_in[1];
    const float* w_theta = (const float*)d_in[2];
    const float* b_theta = (const float*)d_in[3];
    const float* w_phi   = (const float*)d_in[4];
    const float* b_phi   = (const float*)d_in[5];
    const float* w_g     = (const float*)d_in[6];
    const float* b_g     = (const float*)d_in[7];
    const float* w_gbf   = (const float*)d_in[8];
    const float* b_gbf   = (const float*)d_in[9];
    const float* w_W     = (const float*)d_in[10];
    const float* b_W     = (const float*)d_in[11];
    const float* gamma   = (const float*)d_in[12];
    const float* beta    = (const float*)d_in[13];
    const float* mean    = (const float*)d_in[14];
    const float* var     = (const float*)d_in[15];
    float* out = (float*)d_out;

    dim3 g1(NN/32, BB);
    proj_kernel<<<g1, 128>>>(bfimg, x, w_theta, b_theta, w_phi, b_phi,
                             w_g, b_g, w_gbf, b_gbf);

    attn_kernel<<<ATTN_BLOCKS, 128>>>();

    reduce_kernel<<<(BB*17*NN)/256, 256>>>();

    dim3 g3(NN/128, BB, 8);
    epi_kernel<<<g3, 128>>>(bfimg, x, w_W, b_W, gamma, beta, mean, var, out);
}

// round 15
// speedup vs baseline: 1.1091x; 1.0332x over previous
#include <cuda_runtime.h>
#include <cuda_bf16.h>
#include <cstdint>

#define BB 2
#define CC 64
#define CI 16
#define NN 6400            // 80*80
#define KSP 25             // partial slots (key chunks of 256)
#define NITEMS 2500        // 50 qtiles(128) * 2 batches * 25 kchunks
#define ATTN_BLOCKS 608    // 4 per SM (152 SMs on GB300)
#define L2E 1.4426950408889634f

typedef unsigned long long ull;
typedef unsigned int u32;

// ---- global scratch (no allocations allowed) ----
__device__ u32  g_Tb[BB*NN*8];              // theta*log2e bf16x2 words [b][q][8]
__device__ u32  g_Pb[BB*NN*8];              // phi bf16x2 words [b][k][8]
__device__ __nv_bfloat16 g_Gv[(size_t)BB*NN*32];   // values [b][n][32ch]
__device__ u32  g_partw[(size_t)KSP*BB*17*NN];     // partials: 16 ch-pair planes + wsum
__device__ float g_ysum[(size_t)BB*34*NN];         // reduced (34 planes; 33 used)
__device__ unsigned g_ctr;

// =================== low-level helpers ===================
__device__ __forceinline__ u32 smem_u32(const void* p) {
    u32 a; asm("{ .reg .u64 t; cvta.to.shared.u64 t, %1; cvt.u32.u64 %0, t; }"
               : "=r"(a) : "l"(p));
    return a;
}
__device__ __forceinline__ void cp16(u32 dst, const void* src) {
    asm volatile("cp.async.cg.shared.global [%0], [%1], 16;" :: "r"(dst), "l"(src));
}
#define CP_COMMIT() asm volatile("cp.async.commit_group;" ::: "memory")
#define CP_WAIT(n)  asm volatile("cp.async.wait_group %0;" :: "n"(n) : "memory")

__device__ __forceinline__ void ldsm_x4(u32& r0, u32& r1, u32& r2, u32& r3, u32 a) {
    asm volatile("ldmatrix.sync.aligned.m8n8.x4.shared.b16 {%0,%1,%2,%3}, [%4];"
                 : "=r"(r0), "=r"(r1), "=r"(r2), "=r"(r3) : "r"(a));
}
__device__ __forceinline__ void ldsm_x4t(u32& r0, u32& r1, u32& r2, u32& r3, u32 a) {
    asm volatile("ldmatrix.sync.aligned.m8n8.x4.trans.shared.b16 {%0,%1,%2,%3}, [%4];"
                 : "=r"(r0), "=r"(r1), "=r"(r2), "=r"(r3) : "r"(a));
}
__device__ __forceinline__ void mma_bf16(float* d, const u32* a, const u32* b) {
    asm volatile(
        "mma.sync.aligned.m16n8k16.row.col.f32.bf16.bf16.f32 "
        "{%0,%1,%2,%3}, {%4,%5,%6,%7}, {%8,%9}, {%0,%1,%2,%3};"
        : "+f"(d[0]), "+f"(d[1]), "+f"(d[2]), "+f"(d[3])
        : "r"(a[0]), "r"(a[1]), "r"(a[2]), "r"(a[3]), "r"(b[0]), "r"(b[1]));
}

// MUFU 2^x — separate pipe from FMA, rt 8/SMSP, 1 issue slot per value
__device__ __forceinline__ float ex2m(float x) {
    float r; asm("ex2.approx.f32 %0, %1;" : "=f"(r) : "f"(x)); return r;
}
// pack (lo,hi) f32 -> bf16x2 word {lo | hi<<16}
__device__ __forceinline__ u32 packbf2(float lo, float hi) {
    u32 w;
    asm("cvt.rn.bf16x2.f32 %0, %1, %2;" : "=r"(w) : "f"(hi), "f"(lo));
    return w;
}

// ================== Phase 1: projections (bf16 out) + ctr reset ==================
__global__ __launch_bounds__(128) void proj_kernel(
    const float* __restrict__ bfimg, const float* __restrict__ x,
    const float* __restrict__ w_theta, const float* __restrict__ b_theta,
    const float* __restrict__ w_phi,   const float* __restrict__ b_phi,
    const float* __restrict__ w_g,     const float* __restrict__ b_g,
    const float* __restrict__ w_gbf,   const float* __restrict__ b_gbf)
{
    if (blockIdx.x == 0 && blockIdx.y == 0 && threadIdx.x == 0) g_ctr = 0u;

    __shared__ __align__(16) float wS[4][CC*CI];
    __shared__ __align__(16) float sB[CC*32];
    __shared__ __align__(16) float sX[CC*32];
    int tid = threadIdx.x;
    for (int idx = tid; idx < CC*CI; idx += 128) {
        int i = idx / CC, c = idx % CC;
        wS[0][c*CI+i] = w_theta[idx] * L2E;    // theta pre-scaled by log2(e)
        wS[1][c*CI+i] = w_phi[idx];
        wS[2][c*CI+i] = w_g[idx];
        wS[3][c*CI+i] = w_gbf[idx];
    }
    int b  = blockIdx.y;
    int n0 = blockIdx.x * 32;
    {
        const float4* gb = (const float4*)(bfimg + (size_t)b*CC*NN + n0);
        const float4* gx = (const float4*)(x     + (size_t)b*CC*NN + n0);
        #pragma unroll
        for (int k = 0; k < 4; k++) {
            int idx = tid + k*128;
            int c = idx >> 3, f = idx & 7;
            ((float4*)sB)[c*8 + f] = gb[(size_t)c*(NN/4) + f];
            ((float4*)sX)[c*8 + f] = gx[(size_t)c*(NN/4) + f];
        }
    }
    __syncthreads();

    int w = tid >> 5, lane = tid & 31;
    int n = n0 + lane;
    const float* src  = (w == 2) ? sX : sB;
    const float* bias = (w == 0) ? b_theta : (w == 1) ? b_phi : (w == 2) ? b_g : b_gbf;
    const float* wm   = wS[w];
    float bsc = (w == 0) ? L2E : 1.0f;

    float a[CI];
    #pragma unroll
    for (int i = 0; i < CI; i++) a[i] = bias[i] * bsc;
    #pragma unroll 8
    for (int c = 0; c < CC; c++) {
        float v = src[c*32 + lane];
        #pragma unroll
        for (int i = 0; i < CI; i++)
            a[i] = fmaf(wm[c*CI+i], v, a[i]);
    }

    u32 words[8];
    #pragma unroll
    for (int i = 0; i < 8; i++)
        words[i] = packbf2(a[2*i], a[2*i+1]);

    if (w < 2) {
        u32* o = ((w == 0) ? g_Tb : g_Pb) + ((size_t)b*NN + n)*8;
        #pragma unroll
        for (int i = 0; i < 8; i++) o[i] = words[i];
    } else {
        u32* o = (u32*)(g_Gv + ((size_t)b*NN + n)*32) + (w - 2)*8;
        #pragma unroll
        for (int i = 0; i < 8; i++) o[i] = words[i];
    }
}

// ===== Phase 2: HMMA flash attention (qtile=128, occ 4, cross-item pipeline) =====
#define PHI_BYTES (128*48)
#define VROW 96
#define TILE_BYTES (PHI_BYTES + 128*VROW)

__device__ __forceinline__ void load_tile(u32 bufb, int b, int k0, int tid) {
    u32 pdst = bufb + (u32)tid*48;
    const char* psrc = (const char*)(g_Pb + ((size_t)b*NN + k0 + tid)*8);
    cp16(pdst, psrc); cp16(pdst + 16, psrc + 16);
    u32 vdst = bufb + PHI_BYTES + (u32)tid*VROW;
    const char* vsrc = (const char*)(g_Gv + ((size_t)b*NN + k0 + tid)*32);
    #pragma unroll
    for (int i = 0; i < 4; i++) cp16(vdst + 16*i, vsrc + 16*i);
}

// process one 128-key half-tile from buffer `bufb`, accumulating y
// exp: 100% MUFU ex2 (1 issue slot/value; FMA pipe freed entirely)
__device__ __forceinline__ void process_half(
    u32 bufb, u32 phi_off, u32 v_off, const u32 qa[2][4], float y[2][5][4])
{
    u32 phibase = bufb + phi_off;
    u32 vbase   = bufb + PHI_BYTES + v_off;
    #pragma unroll
    for (int kq4 = 0; kq4 < 4; kq4++) {
        int kq = kq4 * 32;
        u32 pb[4][2];
        ldsm_x4(pb[0][0], pb[0][1], pb[1][0], pb[1][1], phibase + (u32)(kq)*48);
        ldsm_x4(pb[2][0], pb[2][1], pb[3][0], pb[3][1], phibase + (u32)(kq + 16)*48);

        u32 pa[2][2][4];
        #pragma unroll
        for (int m = 0; m < 2; m++) {
            float S[4][4];
            #pragma unroll
            for (int j = 0; j < 4; j++) {
                S[j][0] = S[j][1] = S[j][2] = S[j][3] = 0.0f;
                mma_bf16(S[j], qa[m], pb[j]);
            }
            #pragma unroll
            for (int j = 0; j < 4; j++) {
                float e0 = ex2m(S[j][0]);
                float e1 = ex2m(S[j][1]);
                float e2 = ex2m(S[j][2]);
                float e3 = ex2m(S[j][3]);
                pa[m][j >> 1][(j & 1)*2 + 0] = packbf2(e0, e1);
                pa[m][j >> 1][(j & 1)*2 + 1] = packbf2(e2, e3);
            }
        }

        #pragma unroll
        for (int c = 0; c < 2; c++) {
            u32 row = vbase + (u32)(kq + c*16)*VROW;
            u32 vb[4][2], vw[4];
            ldsm_x4t(vb[0][0], vb[0][1], vb[1][0], vb[1][1], row);
            ldsm_x4t(vb[2][0], vb[2][1], vb[3][0], vb[3][1], row + 32);
            ldsm_x4t(vw[0], vw[1], vw[2], vw[3], row + 64);  // ones col
            #pragma unroll
            for (int m = 0; m < 2; m++) {
                #pragma unroll
                for (int nt = 0; nt < 4; nt++)
                    mma_bf16(y[m][nt], pa[m][c], vb[nt]);
                mma_bf16(y[m][4], pa[m][c], vw);   // wsum tile
            }
        }
    }
}

__global__ __launch_bounds__(128, 4) void attn_kernel()
{
    __shared__ __align__(16) char smbuf[2][TILE_BYTES];
    __shared__ unsigned itemSlot[2];

    int tid  = threadIdx.x;
    int wid  = tid >> 5;
    int lane = tid & 31;
    int g = lane >> 2, t = lane & 3;
    u32 sb0 = smem_u32(smbuf[0]);
    u32 sb1 = smem_u32(smbuf[1]);

    // one-time init of the V pad region (ones column at ch32, zeros after)
    #pragma unroll
    for (int bu = 0; bu < 2; bu++) {
        u32* p = (u32*)(smbuf[bu] + PHI_BYTES + tid*VROW + 64);
        p[0] = 0x00003F80u;   // bf16(1.0) in ch32, ch33 = 0
        #pragma unroll
        for (int i = 1; i < 8; i++) p[i] = 0u;
    }

    u32 phi_off = (u32)((((lane>>4)&1)*8 + (lane&7))*48 + ((lane>>3)&1)*16);
    u32 v_off   = (u32)((((lane>>3)&1)*8 + (lane&7))*VROW + ((lane>>4)&1)*16);

    if (tid == 0) itemSlot[0] = atomicAdd(&g_ctr, 1u);
    __syncthreads();
    unsigned item = itemSlot[0];
    if (item < NITEMS) {
        int kc0 = item % KSP;
        int bq0 = item / KSP;
        load_tile(sb0, bq0 & 1, kc0*256,       tid); CP_COMMIT();
        load_tile(sb1, bq0 & 1, kc0*256 + 128, tid); CP_COMMIT();
    }

    while (item < NITEMS) {
        int kc = item % KSP;
        int bqt = item / KSP;
        int b = bqt & 1, qt = bqt >> 1;
        int q0w = qt*128 + wid*32;

        u32 qa[2][4];
        #pragma unroll
        for (int m = 0; m < 2; m++) {
            const u32* t0 = g_Tb + ((size_t)b*NN + q0w + m*16 + g)*8;
            const u32* t8 = t0 + 8*8;
            qa[m][0] = t0[t];     qa[m][1] = t8[t];
            qa[m][2] = t0[t + 4]; qa[m][3] = t8[t + 4];
        }

        float y[2][5][4];   // 4 value n-tiles + 1 wsum n-tile
        #pragma unroll
        for (int m = 0; m < 2; m++)
            #pragma unroll
            for (int nt = 0; nt < 5; nt++)
                #pragma unroll
                for (int d = 0; d < 4; d++) y[m][nt][d] = 0.0f;

        CP_WAIT(1);               // tile0 of current item ready
        __syncthreads();

        process_half(sb0, phi_off, v_off, qa, y);

        if (tid == 0) itemSlot[1] = atomicAdd(&g_ctr, 1u);   // prefetch next id

        CP_WAIT(0);               // tile1 ready; buf0 free
        __syncthreads();          // also publishes itemSlot[1]

        unsigned nxt = itemSlot[1];
        if (nxt < NITEMS) {       // prefetch next item's tile0 into buf0
            int kcn = nxt % KSP;
            int bn  = (nxt / KSP) & 1;
            load_tile(sb0, bn, kcn*256, tid); CP_COMMIT();
        }

        process_half(sb1, phi_off, v_off, qa, y);

        __syncthreads();          // buf1 fully consumed
        if (nxt < NITEMS) {       // prefetch next item's tile1 into buf1
            int kcn = nxt % KSP;
            int bn  = (nxt / KSP) & 1;
            load_tile(sb1, bn, kcn*256 + 128, tid); CP_COMMIT();
        }

        // ---- write partials: bf16x2-packed channel pairs (4B coalesced) ----
        u32* part = g_partw + ((size_t)(kc*BB + b)*17)*NN;
        #pragma unroll
        for (int m = 0; m < 2; m++) {
            int rg = q0w + m*16 + g;
            #pragma unroll
            for (int nt = 0; nt < 4; nt++) {
                int cp = nt*4 + t;            // channel pair (2cp, 2cp+1)
                part[(size_t)cp*NN + rg]     = packbf2(y[m][nt][0], y[m][nt][1]);
                part[(size_t)cp*NN + rg + 8] = packbf2(y[m][nt][2], y[m][nt][3]);
            }
            if (t == 0) {                     // wsum plane (lo half used)
                part[(size_t)16*NN + rg]     = packbf2(y[m][4][0], 0.0f);
                part[(size_t)16*NN + rg + 8] = packbf2(y[m][4][2], 0.0f);
            }
        }

        item = nxt;
    }
}

// ============ Phase 3a: parallel partial reduction (bf16x2 -> f32) ============
__global__ __launch_bounds__(256) void reduce_kernel()
{
    const size_t STR = (size_t)BB*17*NN;
    size_t idx = (size_t)blockIdx.x * 256 + threadIdx.x;   // [b][cp][n]
    const u32* p = g_partw + idx;
    float v0 = 0.0f, v1 = 0.0f;
    #pragma unroll
    for (int ks = 0; ks < KSP; ks++) {
        u32 w = p[ks*STR];
        v0 += __uint_as_float(w << 16);
        v1 += __uint_as_float(w & 0xFFFF0000u);
    }
    int b   = (int)(idx / (17*NN));
    int rem = (int)(idx - (size_t)b*17*NN);
    int cp  = rem / NN;
    int n   = rem - cp*NN;
    float* o = g_ysum + ((size_t)b*34 + 2*cp)*NN + n;
    o[0]  = v0;
    o[NN] = v1;
}

// ============ Phase 3b: folded BN(W y) + residual, 8 ch/block ============
__global__ __launch_bounds__(128) void epi_kernel(
    const float* __restrict__ bfimg, const float* __restrict__ x,
    const float* __restrict__ w_W,   const float* __restrict__ b_W,
    const float* __restrict__ gamma, const float* __restrict__ beta,
    const float* __restrict__ mean,  const float* __restrict__ var,
    float* __restrict__ out)
{
    __shared__ __align__(16) float Wp[8*CI];
    __shared__ float bp[8];
    int tid = threadIdx.x;
    int oct = blockIdx.z;             // 0..7: 8 output channels each
    int cbase = oct * 8;
    if (tid < 8) {
        int c = cbase + tid;
        float inv = rsqrtf(var[c] + 1e-5f);
        float al  = gamma[c] * inv;
        bp[tid]   = beta[c] + al * (b_W[c] - mean[c]);
    }
    if (tid < 8*CI) {
        int c = cbase + tid / CI;
        float inv = rsqrtf(var[c] + 1e-5f);
        Wp[tid] = gamma[c] * inv * w_W[c*CI + (tid % CI)];
    }
    __syncthreads();

    int b = blockIdx.y;
    int n = blockIdx.x * 128 + tid;

    const float* ys = g_ysum + (size_t)b*34*NN + n;
    float y[32];
    #pragma unroll
    for (int j = 0; j < 32; j++) y[j] = ys[(size_t)j*NN];
    float invws = 1.0f / ys[(size_t)32*NN];
    #pragma unroll
    for (int j = 0; j < 32; j++) y[j] *= invws;

    const float* xr = x     + (size_t)b*CC*NN + n;
    const float* br = bfimg + (size_t)b*CC*NN + n;
    float* o1 = out + (size_t)b*2*CC*NN + n;
    float* o2 = o1 + (size_t)CC*NN;

    #pragma unroll
    for (int ci = 0; ci < 8; ci++) {
        int c = cbase + ci;
        const float4* w4 = (const float4*)&Wp[ci*CI];
        float4 wa = w4[0], wb = w4[1], wc = w4[2], wd = w4[3];
        float base = bp[ci];
        float r1 = base + xr[(size_t)c*NN];
        float r2 = base + br[(size_t)c*NN];
        r1 = fmaf(wa.x, y[0],  r1); r1 = fmaf(wa.y, y[1],  r1);
        r1 = fmaf(wa.z, y[2],  r1); r1 = fmaf(wa.w, y[3],  r1);
        r1 = fmaf(wb.x, y[4],  r1); r1 = fmaf(wb.y, y[5],  r1);
        r1 = fmaf(wb.z, y[6],  r1); r1 = fmaf(wb.w, y[7],  r1);
        r1 = fmaf(wc.x, y[8],  r1); r1 = fmaf(wc.y, y[9],  r1);
        r1 = fmaf(wc.z, y[10], r1); r1 = fmaf(wc.w, y[11], r1);
        r1 = fmaf(wd.x, y[12], r1); r1 = fmaf(wd.y, y[13], r1);
        r1 = fmaf(wd.z, y[14], r1); r1 = fmaf(wd.w, y[15], r1);
        r2 = fmaf(wa.x, y[16], r2); r2 = fmaf(wa.y, y[17], r2);
        r2 = fmaf(wa.z, y[18], r2); r2 = fmaf(wa.w, y[19], r2);
        r2 = fmaf(wb.x, y[20], r2); r2 = fmaf(wb.y, y[21], r2);
        r2 = fmaf(wb.z, y[22], r2); r2 = fmaf(wb.w, y[23], r2);
        r2 = fmaf(wc.x, y[24], r2); r2 = fmaf(wc.y, y[25], r2);
        r2 = fmaf(wc.z, y[26], r2); r2 = fmaf(wc.w, y[27], r2);
        r2 = fmaf(wd.x, y[28], r2); r2 = fmaf(wd.y, y[29], r2);
        r2 = fmaf(wd.z, y[30], r2); r2 = fmaf(wd.w, y[31], r2);
        o1[(size_t)c*NN] = r1;
        o2[(size_t)c*NN] = r2;
    }
}

extern "C" void kernel_launch(void* const* d_in, const int* in_sizes, int n_in,
                              void* d_out, int out_size)
{
    (void)in_sizes; (void)n_in; (void)out_size;
    const float* bfimg   = (const float*)d_in[0];
    const float* x       = (const float*)d_in[1];
    const float* w_theta = (const float*)d_in[2];
    const float* b_theta = (const float*)d_in[3];
    const float* w_phi   = (const float*)d_in[4];
    const float* b_phi   = (const float*)d_in[5];
    const float* w_g     = (const float*)d_in[6];
    const float* b_g     = (const float*)d_in[7];
    const float* w_gbf   = (const float*)d_in[8];
    const float* b_gbf   = (const float*)d_in[9];
    const float* w_W     = (const float*)d_in[10];
    const float* b_W     = (const float*)d_in[11];
    const float* gamma   = (const float*)d_in[12];
    const float* beta    = (const float*)d_in[13];
    const float* mean    = (const float*)d_in[14];
    const float* var     = (const float*)d_in[15];
    float* out = (float*)d_out;

    dim3 g1(NN/32, BB);
    proj_kernel<<<g1, 128>>>(bfimg, x, w_theta, b_theta, w_phi, b_phi,
                             w_g, b_g, w_gbf, b_gbf);

    attn_kernel<<<ATTN_BLOCKS, 128>>>();

    reduce_kernel<<<(BB*17*NN)/256, 256>>>();

    dim3 g3(NN/128, BB, 8);
    epi_kernel<<<g3, 128>>>(bfimg, x, w_W, b_W, gamma, beta, mean, var, out);
}